// round 1
// baseline (speedup 1.0000x reference)
#include <cuda_runtime.h>
#include <cstdint>

// TPlanesEnc: B=4, N=131072, P=512, F=32.
// d_in[0] = coords  [B, N, 3]   fp32  (1,572,864 elems)
// d_in[1] = tplanes [3, P, P, F] fp32 (25,165,824 elems)
// d_out   = out     [B, N, 3*F] fp32 (50,331,648 elems)
//
// Strategy: one warp per point; lane = feature channel. 12 texel loads per
// lane (4 corners x 3 planes), each warp-coalesced to a 128B line. Axis
// interpolation params computed once per point, reused across planes.
// Output stored with .cs (streaming) hint so the 201MB write stream doesn't
// evict the 100MB tplanes working set from L2.

#define PS 512
#define FD 32

__global__ __launch_bounds__(256, 8)
void tplanes_kernel(const float* __restrict__ coords,
                    const float* __restrict__ tpl,
                    float* __restrict__ out,
                    int M)
{
    const int gtid = blockIdx.x * blockDim.x + threadIdx.x;
    const int warp = gtid >> 5;
    const int lane = threadIdx.x & 31;
    if (warp >= M) return;

    // Per-point coords (uniform across warp -> broadcast loads)
    const float cx = __ldg(&coords[warp * 3 + 0]);
    const float cy = __ldg(&coords[warp * 3 + 1]);
    const float cz = __ldg(&coords[warp * 3 + 2]);

    // Axis interpolation params: t in [0,1], texel space clamp-to-edge
    int i0[3], i1[3];
    float fr[3];
    {
        const float c3[3] = {cx, cy, cz};
#pragma unroll
        for (int a = 0; a < 3; a++) {
            float t = c3[a] * 0.5f + 0.5f;
            float x = t * (float)PS - 0.5f;
            x = fminf(fmaxf(x, 0.0f), (float)(PS - 1));
            float x0 = floorf(x);
            int xi0 = (int)x0;
            i0[a] = xi0;
            i1[a] = min(xi0 + 1, PS - 1);
            fr[a] = x - x0;
        }
    }

    // plane 0 samples (u=x, v=y); plane 1 (u=x, v=z); plane 2 (u=z, v=y)
    const int uax[3] = {0, 0, 2};
    const int vax[3] = {1, 2, 1};

    // Compute all 12 addresses first, then issue all loads (MLP), then math.
    const float* addr[12];
#pragma unroll
    for (int p = 0; p < 3; p++) {
        const float* base = tpl + (size_t)p * PS * PS * FD + lane;
        const int u0 = i0[uax[p]], u1 = i1[uax[p]];
        const int v0 = i0[vax[p]], v1 = i1[vax[p]];
        addr[p * 4 + 0] = base + ((size_t)v0 * PS + u0) * FD;  // f00
        addr[p * 4 + 1] = base + ((size_t)v0 * PS + u1) * FD;  // f01
        addr[p * 4 + 2] = base + ((size_t)v1 * PS + u0) * FD;  // f10
        addr[p * 4 + 3] = base + ((size_t)v1 * PS + u1) * FD;  // f11
    }

    float tex[12];
#pragma unroll
    for (int i = 0; i < 12; i++) tex[i] = __ldg(addr[i]);

    float* op = out + (size_t)warp * (3 * FD) + lane;
#pragma unroll
    for (int p = 0; p < 3; p++) {
        const float fx = fr[uax[p]];
        const float fy = fr[vax[p]];
        const float f00 = tex[p * 4 + 0];
        const float f01 = tex[p * 4 + 1];
        const float f10 = tex[p * 4 + 2];
        const float f11 = tex[p * 4 + 3];
        const float top = f00 + (f01 - f00) * fx;
        const float bot = f10 + (f11 - f10) * fx;
        const float r   = top + (bot - top) * fy;
        __stcs(op + p * FD, r);
    }
}

extern "C" void kernel_launch(void* const* d_in, const int* in_sizes, int n_in,
                              void* d_out, int out_size)
{
    const float* coords = (const float*)d_in[0];
    const float* tpl    = (const float*)d_in[1];
    float* out          = (float*)d_out;

    const int M = in_sizes[0] / 3;           // total points = B*N
    const int warps_per_block = 256 / 32;    // 8
    const int blocks = (M + warps_per_block - 1) / warps_per_block;
    tplanes_kernel<<<blocks, 256>>>(coords, tpl, out, M);
}

// round 5
// speedup vs baseline: 1.0060x; 1.0060x over previous
#include <cuda_runtime.h>
#include <cstdint>

// TPlanesEnc: B=4, N=131072, P=512, F=32.
// d_in[0] = coords  [B, N, 3]   fp32
// d_in[1] = tplanes [3, P, P, F] fp32  (96 MB -- fits in 126 MB L2)
// d_out   = out     [B, N, 3*F] fp32   (201 MB streaming)
//
// R3: scalar evict_last via createpolicy + ld.global.nc.L2::cache_hint
// (static .L2::evict_last qualifier is v8/v4-only on sm_103a ptxas).
// Texture reads pinned in L2; output stores stream evict-first (st.global.cs).

#define PS 512
#define FD 32

__device__ __forceinline__ uint64_t make_evict_last_policy() {
    uint64_t pol;
    asm("createpolicy.fractional.L2::evict_last.b64 %0, 1.0;" : "=l"(pol));
    return pol;
}

__device__ __forceinline__ float ldg_hint(const float* p, uint64_t pol) {
    float v;
    asm("ld.global.nc.L2::cache_hint.f32 %0, [%1], %2;"
        : "=f"(v) : "l"(p), "l"(pol));
    return v;
}

__device__ __forceinline__ void stg_streaming(float* p, float v) {
    asm volatile("st.global.cs.f32 [%0], %1;" :: "l"(p), "f"(v) : "memory");
}

__global__ __launch_bounds__(256, 8)
void tplanes_kernel(const float* __restrict__ coords,
                    const float* __restrict__ tpl,
                    float* __restrict__ out,
                    int M)
{
    const int gtid = blockIdx.x * blockDim.x + threadIdx.x;
    const int warp = gtid >> 5;
    const int lane = threadIdx.x & 31;
    if (warp >= M) return;

    const uint64_t pol = make_evict_last_policy();

    // Per-point coords (uniform across warp -> broadcast loads)
    const float cx = __ldg(&coords[warp * 3 + 0]);
    const float cy = __ldg(&coords[warp * 3 + 1]);
    const float cz = __ldg(&coords[warp * 3 + 2]);

    // Axis interpolation params (texel centers, clamp-to-edge)
    int i0[3], i1[3];
    float fr[3];
    {
        const float c3[3] = {cx, cy, cz};
#pragma unroll
        for (int a = 0; a < 3; a++) {
            float t = c3[a] * 0.5f + 0.5f;
            float x = t * (float)PS - 0.5f;
            x = fminf(fmaxf(x, 0.0f), (float)(PS - 1));
            float x0 = floorf(x);
            int xi0 = (int)x0;
            i0[a] = xi0;
            i1[a] = min(xi0 + 1, PS - 1);
            fr[a] = x - x0;
        }
    }

    // plane 0 samples (u=x, v=y); plane 1 (u=x, v=z); plane 2 (u=z, v=y)
    const int uax[3] = {0, 0, 2};
    const int vax[3] = {1, 2, 1};

    // Compute all 12 addresses first, then issue all loads (MLP=12/lane).
    const float* addr[12];
#pragma unroll
    for (int p = 0; p < 3; p++) {
        const float* base = tpl + (size_t)p * PS * PS * FD + lane;
        const int u0 = i0[uax[p]], u1 = i1[uax[p]];
        const int v0 = i0[vax[p]], v1 = i1[vax[p]];
        addr[p * 4 + 0] = base + ((size_t)v0 * PS + u0) * FD;  // f00
        addr[p * 4 + 1] = base + ((size_t)v0 * PS + u1) * FD;  // f01
        addr[p * 4 + 2] = base + ((size_t)v1 * PS + u0) * FD;  // f10
        addr[p * 4 + 3] = base + ((size_t)v1 * PS + u1) * FD;  // f11
    }

    float tex[12];
#pragma unroll
    for (int i = 0; i < 12; i++) tex[i] = ldg_hint(addr[i], pol);

    float* op = out + (size_t)warp * (3 * FD) + lane;
#pragma unroll
    for (int p = 0; p < 3; p++) {
        const float fx = fr[uax[p]];
        const float fy = fr[vax[p]];
        const float f00 = tex[p * 4 + 0];
        const float f01 = tex[p * 4 + 1];
        const float f10 = tex[p * 4 + 2];
        const float f11 = tex[p * 4 + 3];
        const float top = f00 + (f01 - f00) * fx;
        const float bot = f10 + (f11 - f10) * fx;
        const float r   = top + (bot - top) * fy;
        stg_streaming(op + p * FD, r);
    }
}

extern "C" void kernel_launch(void* const* d_in, const int* in_sizes, int n_in,
                              void* d_out, int out_size)
{
    const float* coords = (const float*)d_in[0];
    const float* tpl    = (const float*)d_in[1];
    float* out          = (float*)d_out;

    const int M = in_sizes[0] / 3;           // total points = B*N
    const int warps_per_block = 256 / 32;    // 8
    const int blocks = (M + warps_per_block - 1) / warps_per_block;
    tplanes_kernel<<<blocks, 256>>>(coords, tpl, out, M);
}